// round 1
// baseline (speedup 1.0000x reference)
#include <cuda_runtime.h>
#include <cuda_bf16.h>

// Problem constants
#define LQ 2048
#define SQ 2048
#define NB 2
#define EE 1024
#define HH 16
#define DD 64
#define KSEL 1176          // int(2048 * sigmoid(0.3))

#define GM 4096            // rows (l*N+n) for all GEMMs
#define GK 1024
#define GN 1024
#define BM 128
#define BN 64
#define BK 16

#define TQ 8               // query rows per attention block

// ---------------- scratch (static device memory; no allocation) -------------
__device__ float g_Q [ (size_t)NB*HH*LQ*DD ];   // [n,h,l,d]
__device__ float g_Kt[ (size_t)NB*HH*DD*SQ ];   // [n,h,d,s]  (d-major for coalesced score loads)
__device__ float g_V [ (size_t)NB*HH*SQ*DD ];   // [n,h,s,d]
__device__ float g_O [ (size_t)GM*EE ];         // [l*N+n, e] with e = d*H + h

// ---------------- GEMM: Y[m,j] = sum_k A[m,k]*W[j,k] + bias[j] --------------
// mode 0: write Q[n,h,l,d]; 1: Kt[n,h,d,s]; 2: V[n,h,s,d]; 3: plain [m,j]
__global__ void __launch_bounds__(256)
gemm_kernel(const float* __restrict__ A, const float* __restrict__ W,
            const float* __restrict__ bias, float* __restrict__ out, int mode)
{
    __shared__ float As[BK][BM];
    __shared__ float Bs[BK][BN + 4];

    int tid = threadIdx.x;
    int tx = tid & 15;          // 0..15 -> 4 cols each
    int ty = tid >> 4;          // 0..15 -> 8 rows each
    int m0 = blockIdx.y * BM;
    int n0 = blockIdx.x * BN;

    float acc[8][4];
#pragma unroll
    for (int i = 0; i < 8; i++)
#pragma unroll
        for (int j = 0; j < 4; j++) acc[i][j] = 0.f;

    for (int k0 = 0; k0 < GK; k0 += BK) {
        // load A tile: 128x16 = 512 float4
#pragma unroll
        for (int i = 0; i < 2; i++) {
            int e   = tid + i * 256;
            int row = e >> 2;
            int kq  = e & 3;
            float4 v = *(const float4*)(A + (size_t)(m0 + row) * GK + k0 + kq * 4);
            As[kq*4+0][row] = v.x; As[kq*4+1][row] = v.y;
            As[kq*4+2][row] = v.z; As[kq*4+3][row] = v.w;
        }
        // load W tile: 64x16 = 256 float4
        {
            int row = tid >> 2;
            int kq  = tid & 3;
            float4 v = *(const float4*)(W + (size_t)(n0 + row) * GK + k0 + kq * 4);
            Bs[kq*4+0][row] = v.x; Bs[kq*4+1][row] = v.y;
            Bs[kq*4+2][row] = v.z; Bs[kq*4+3][row] = v.w;
        }
        __syncthreads();
#pragma unroll
        for (int kk = 0; kk < BK; kk++) {
            float a[8], b[4];
            *(float4*)&a[0] = *(const float4*)&As[kk][ty * 8];
            *(float4*)&a[4] = *(const float4*)&As[kk][ty * 8 + 4];
            *(float4*)&b[0] = *(const float4*)&Bs[kk][tx * 4];
#pragma unroll
            for (int i = 0; i < 8; i++)
#pragma unroll
                for (int j = 0; j < 4; j++) acc[i][j] += a[i] * b[j];
        }
        __syncthreads();
    }

    float bb[4];
#pragma unroll
    for (int j = 0; j < 4; j++) bb[j] = bias[n0 + tx * 4 + j];

#pragma unroll
    for (int i = 0; i < 8; i++) {
        int m = m0 + ty * 8 + i;
        int l = m >> 1;          // l (or s); rows are (l*N + n), N=2
        int n = m & 1;
#pragma unroll
        for (int j = 0; j < 4; j++) {
            int jj = n0 + tx * 4 + j;
            float val = acc[i][j] + bb[j];
            int h = jj >> 6;
            int d = jj & 63;
            if (mode == 0) {
                g_Q[ (((size_t)(n*HH + h))*LQ + l)*DD + d ] = val;
            } else if (mode == 1) {
                g_Kt[ (((size_t)(n*HH + h))*DD + d)*SQ + l ] = val;
            } else if (mode == 2) {
                g_V[ (((size_t)(n*HH + h))*SQ + l)*DD + d ] = val;
            } else {
                out[ (size_t)m * GN + jj ] = val;
            }
        }
    }
}

// ---------------- attention: scores -> top-k threshold -> softmax -> @V -----
__device__ __forceinline__ unsigned f2key(float f) {
    unsigned u = __float_as_uint(f);
    return (u & 0x80000000u) ? ~u : (u | 0x80000000u);  // order-preserving
}

// dynamic shared layout (floats):
//   sc   [TQ*SQ]            scores, later unnormalized probs
//   qs   [TQ*DD]
//   red  [8*TQ*DD]          (union: int hist[TQ*256] lives inside red)
//   invz [TQ]
#define SMEM_FLOATS (TQ*SQ + TQ*DD + 8*TQ*DD + TQ)
#define SMEM_BYTES  (SMEM_FLOATS * 4)

__global__ void __launch_bounds__(256)
attn_kernel(const float* __restrict__ Q, const float* __restrict__ Kt,
            const float* __restrict__ V, float* __restrict__ O)
{
    extern __shared__ float smem[];
    float* sc   = smem;
    float* qs   = sc + TQ * SQ;
    float* red  = qs + TQ * DD;
    int*   hist = (int*)red;
    float* invz = red + 8 * TQ * DD;

    int tid  = threadIdx.x;
    int lane = tid & 31;
    int w    = tid >> 5;
    int h  = blockIdx.y;
    int n  = blockIdx.z;
    int nh = n * HH + h;
    int l0 = blockIdx.x * TQ;

    // load q tile [TQ][DD]
    for (int i = tid; i < TQ * DD; i += 256) {
        int r = i >> 6, d = i & 63;
        qs[i] = Q[ (((size_t)nh) * LQ + l0 + r) * DD + d ];
    }
    __syncthreads();

    // ---- scores: thread owns one s per iteration (coalesced Kt loads) ----
    const float* ktb = Kt + (size_t)nh * DD * SQ;
    for (int ss = 0; ss < SQ / 256; ss++) {
        int s = ss * 256 + tid;
        float acc[TQ];
#pragma unroll
        for (int r = 0; r < TQ; r++) acc[r] = 0.f;
#pragma unroll 8
        for (int d = 0; d < DD; d++) {
            float kv = ktb[(size_t)d * SQ + s];
#pragma unroll
            for (int r = 0; r < TQ; r++) acc[r] += qs[r * DD + d] * kv;
        }
#pragma unroll
        for (int r = 0; r < TQ; r++) sc[r * SQ + s] = acc[r] * 0.125f;
    }
    __syncthreads();

    // ---- per-warp: row = w. max, radix-select k-th value, exp, Z ----
    {
        int row = w;
        float* scr = sc + row * SQ;

        float mx = -1e30f;
        for (int i = lane; i < SQ; i += 32) mx = fmaxf(mx, scr[i]);
#pragma unroll
        for (int o = 16; o; o >>= 1) mx = fmaxf(mx, __shfl_xor_sync(~0u, mx, o));

        unsigned prefix = 0, maskHi = 0;
        int remaining = KSEL;
        int* hrow = hist + row * 256;
#pragma unroll
        for (int pass = 0; pass < 4; pass++) {
            int shift = 24 - pass * 8;
            for (int i = lane; i < 256; i += 32) hrow[i] = 0;
            __syncwarp();
            for (int i = lane; i < SQ; i += 32) {
                unsigned key = f2key(scr[i]);
                if ((key & maskHi) == (prefix & maskHi))
                    atomicAdd(&hrow[(key >> shift) & 255], 1);
            }
            __syncwarp();
            int chunk = 0;
#pragma unroll
            for (int b = 0; b < 8; b++) chunk += hrow[lane * 8 + b];
            int suf = chunk;
#pragma unroll
            for (int o = 1; o < 32; o <<= 1) {
                int v = __shfl_down_sync(~0u, suf, o);
                if (lane + o < 32) suf += v;
            }
            unsigned bal = __ballot_sync(~0u, suf >= remaining);
            int Ls   = 31 - __clz((int)bal);
            int sufL = __shfl_sync(~0u, suf,   Ls);
            int chL  = __shfl_sync(~0u, chunk, Ls);
            int selByte = 0;
            if (lane == 0) {
                int cum = sufL - chL;                 // count in buckets > this chunk
                for (int b = 7; b >= 0; b--) {
                    int hc = hrow[Ls * 8 + b];
                    if (cum + hc >= remaining) { selByte = Ls * 8 + b; remaining -= cum; break; }
                    cum += hc;
                }
            }
            selByte   = __shfl_sync(~0u, selByte, 0);
            remaining = __shfl_sync(~0u, remaining, 0);
            prefix |= ((unsigned)selByte) << shift;
            maskHi |= 0xFFu << shift;
            __syncwarp();
        }
        unsigned thrKey = prefix;   // key of the KSEL-th largest score

        float z = 0.f;
        for (int i = lane; i < SQ; i += 32) {
            float v = scr[i];
            float p = (f2key(v) >= thrKey) ? __expf(v - mx) : 0.f;
            scr[i] = p;
            z += p;
        }
#pragma unroll
        for (int o = 16; o; o >>= 1) z += __shfl_xor_sync(~0u, z, o);
        if (lane == 0) invz[row] = 1.f / z;
    }
    __syncthreads();

    // ---- attn @ V : warp w handles s in [w*256, w*256+256), lane = d ----
    const float* vb = V + (size_t)nh * SQ * DD;
    float a0[TQ], a1[TQ];
#pragma unroll
    for (int r = 0; r < TQ; r++) { a0[r] = 0.f; a1[r] = 0.f; }
    for (int s = w * 256; s < w * 256 + 256; s++) {
        float v0 = vb[(size_t)s * DD + lane];
        float v1 = vb[(size_t)s * DD + lane + 32];
#pragma unroll
        for (int r = 0; r < TQ; r++) {
            float p = sc[r * SQ + s];
            a0[r] += p * v0;
            a1[r] += p * v1;
        }
    }
    float* redp = red + w * TQ * DD;
#pragma unroll
    for (int r = 0; r < TQ; r++) {
        redp[r * DD + lane]      = a0[r];
        redp[r * DD + lane + 32] = a1[r];
    }
    __syncthreads();

    // ---- cross-warp reduce, normalize, write O[l*N+n][d*H+h] ----
    for (int o = tid; o < TQ * DD; o += 256) {
        int r = o >> 6, d = o & 63;
        float sum = 0.f;
#pragma unroll
        for (int ww = 0; ww < 8; ww++) sum += red[ww * TQ * DD + o];
        float val = sum * invz[r];
        int l = l0 + r;
        O[ ((size_t)(l * NB + n)) * EE + d * HH + h ] = val;
    }
}

// ---------------- launch ----------------------------------------------------
extern "C" void kernel_launch(void* const* d_in, const int* in_sizes, int n_in,
                              void* d_out, int out_size)
{
    const float* query = (const float*)d_in[0];
    const float* key   = (const float*)d_in[1];
    const float* value = (const float*)d_in[2];
    const float* Wq    = (const float*)d_in[3];
    const float* bq    = (const float*)d_in[4];
    const float* Wk    = (const float*)d_in[5];
    const float* bk    = (const float*)d_in[6];
    const float* Wv    = (const float*)d_in[7];
    const float* bv    = (const float*)d_in[8];
    const float* Wo    = (const float*)d_in[9];
    const float* bo    = (const float*)d_in[10];
    float* out = (float*)d_out;

    float *Qp, *Ktp, *Vp, *Op;
    cudaGetSymbolAddress((void**)&Qp,  g_Q);
    cudaGetSymbolAddress((void**)&Ktp, g_Kt);
    cudaGetSymbolAddress((void**)&Vp,  g_V);
    cudaGetSymbolAddress((void**)&Op,  g_O);

    cudaFuncSetAttribute(attn_kernel, cudaFuncAttributeMaxDynamicSharedMemorySize, SMEM_BYTES);

    dim3 gg(GN / BN, GM / BM);   // (16, 32)
    gemm_kernel<<<gg, 256>>>(query, Wq, bq, nullptr, 0);
    gemm_kernel<<<gg, 256>>>(key,   Wk, bk, nullptr, 1);
    gemm_kernel<<<gg, 256>>>(value, Wv, bv, nullptr, 2);

    dim3 ag(LQ / TQ, HH, NB);    // (256, 16, 2) — l fastest for L2 reuse of K/V
    attn_kernel<<<ag, 256, SMEM_BYTES>>>(Qp, Ktp, Vp, Op);

    gemm_kernel<<<gg, 256>>>(Op, Wo, bo, out, 3);
}

// round 2
// speedup vs baseline: 1.0580x; 1.0580x over previous
#include <cuda_runtime.h>
#include <cuda_bf16.h>

#define LQ 2048
#define SQ 2048
#define NB 2
#define EE 1024
#define HH 16
#define DD 64
#define KSEL 1176          // int(2048 * sigmoid(0.3))

#define GM 4096
#define GK 1024
#define GN 1024
#define BM 128
#define BN 128
#define BK 16
#define TQ 8

typedef unsigned long long u64;

// ---------------- f32x2 packed helpers (sm_100+) ----------------------------
__device__ __forceinline__ u64 pk2(float lo, float hi) {
    u64 r; asm("mov.b64 %0, {%1, %2};" : "=l"(r) : "f"(lo), "f"(hi)); return r;
}
__device__ __forceinline__ u64 dup2(float x) {
    u64 r; asm("mov.b64 %0, {%1, %1};" : "=l"(r) : "f"(x)); return r;
}
__device__ __forceinline__ void fma2(u64 &d, u64 a, u64 b) {
    asm("fma.rn.f32x2 %0, %1, %2, %0;" : "+l"(d) : "l"(a), "l"(b));
}
__device__ __forceinline__ float2 up2(u64 v) {
    float2 f; asm("mov.b64 {%0, %1}, %2;" : "=f"(f.x), "=f"(f.y) : "l"(v)); return f;
}

// ---------------- scratch ----------------------------------------------------
__device__ float g_Q [ (size_t)NB*HH*LQ*DD ];   // [n,h,l,d]
__device__ float g_Kt[ (size_t)NB*HH*DD*SQ ];   // [n,h,d,s]
__device__ float g_V [ (size_t)NB*HH*SQ*DD ];   // [n,h,s,d]
__device__ float g_O [ (size_t)GM*EE ];         // [l*N+n, e=d*H+h]

// ---------------- GEMM body: Y[m,j] = sum_k A[m,k]*W[j,k] + bias[j] ---------
__device__ __forceinline__ void gemm_body(
    const float* __restrict__ A, const float* __restrict__ W,
    const float* __restrict__ bias, float* __restrict__ out, int mode)
{
    __shared__ float As[BK][BM + 4];
    __shared__ float Bs[BK][BN + 4];

    const int tid = threadIdx.x;
    const int tx = tid & 15;      // 8 cols each
    const int ty = tid >> 4;      // 8 rows each
    const int m0 = blockIdx.y * BM;
    const int n0 = blockIdx.x * BN;

    u64 acc[8][4];
#pragma unroll
    for (int i = 0; i < 8; i++)
#pragma unroll
        for (int j = 0; j < 4; j++) acc[i][j] = 0ull;

    for (int k0 = 0; k0 < GK; k0 += BK) {
#pragma unroll
        for (int i = 0; i < 2; i++) {
            int e   = tid + i * 256;
            int row = e >> 2;
            int kq  = e & 3;
            float4 va = *(const float4*)(A + (size_t)(m0 + row) * GK + k0 + kq * 4);
            As[kq*4+0][row] = va.x; As[kq*4+1][row] = va.y;
            As[kq*4+2][row] = va.z; As[kq*4+3][row] = va.w;
            float4 vb = *(const float4*)(W + (size_t)(n0 + row) * GK + k0 + kq * 4);
            Bs[kq*4+0][row] = vb.x; Bs[kq*4+1][row] = vb.y;
            Bs[kq*4+2][row] = vb.z; Bs[kq*4+3][row] = vb.w;
        }
        __syncthreads();
#pragma unroll
        for (int kk = 0; kk < BK; kk++) {
            float4 a0 = *(const float4*)&As[kk][ty * 8];
            float4 a1 = *(const float4*)&As[kk][ty * 8 + 4];
            ulonglong2 bb0 = *(const ulonglong2*)&Bs[kk][tx * 8];
            ulonglong2 bb1 = *(const ulonglong2*)&Bs[kk][tx * 8 + 4];
            float a[8] = {a0.x, a0.y, a0.z, a0.w, a1.x, a1.y, a1.z, a1.w};
#pragma unroll
            for (int i = 0; i < 8; i++) {
                u64 ad = dup2(a[i]);
                fma2(acc[i][0], ad, bb0.x);
                fma2(acc[i][1], ad, bb0.y);
                fma2(acc[i][2], ad, bb1.x);
                fma2(acc[i][3], ad, bb1.y);
            }
        }
        __syncthreads();
    }

    float bb[8];
#pragma unroll
    for (int j = 0; j < 8; j++) bb[j] = bias[n0 + tx * 8 + j];

#pragma unroll
    for (int i = 0; i < 8; i++) {
        int m = m0 + ty * 8 + i;
        int l = m >> 1;
        int n = m & 1;
        float vals[8];
#pragma unroll
        for (int j = 0; j < 4; j++) {
            float2 f = up2(acc[i][j]);
            vals[2*j]   = f.x + bb[2*j];
            vals[2*j+1] = f.y + bb[2*j+1];
        }
#pragma unroll
        for (int j = 0; j < 8; j++) {
            int c = n0 + tx * 8 + j;
            int h = c >> 6, d = c & 63;
            float v = vals[j];
            if (mode == 0)      g_Q [ (((size_t)(n*HH + h))*LQ + l)*DD + d ] = v;
            else if (mode == 1) g_Kt[ (((size_t)(n*HH + h))*DD + d)*SQ + l ] = v;
            else if (mode == 2) g_V [ (((size_t)(n*HH + h))*SQ + l)*DD + d ] = v;
            else                out [ (size_t)m * GN + c ] = v;
        }
    }
}

__global__ void __launch_bounds__(256) gemm_qkv_kernel(
    const float* __restrict__ q, const float* __restrict__ k, const float* __restrict__ v,
    const float* __restrict__ Wq, const float* __restrict__ bq,
    const float* __restrict__ Wk, const float* __restrict__ bk,
    const float* __restrict__ Wv, const float* __restrict__ bv)
{
    int z = blockIdx.z;
    const float* A = (z == 0) ? q  : (z == 1) ? k  : v;
    const float* W = (z == 0) ? Wq : (z == 1) ? Wk : Wv;
    const float* B = (z == 0) ? bq : (z == 1) ? bk : bv;
    gemm_body(A, W, B, nullptr, z);
}

__global__ void __launch_bounds__(256) gemm_out_kernel(
    const float* __restrict__ A, const float* __restrict__ W,
    const float* __restrict__ b, float* __restrict__ out)
{
    gemm_body(A, W, b, out, 3);
}

// ---------------- attention --------------------------------------------------
// smem: q2[4*DD] u64 | sc[TQ*SQ] f32 | red[8*TQ*DD] f32 | invz[TQ]
#define SMEM_FLOATS (2*4*DD + TQ*SQ + 8*TQ*DD + TQ)
#define SMEM_BYTES  (SMEM_FLOATS * 4)

__global__ void __launch_bounds__(256)
attn_kernel(const float* __restrict__ Q, const float* __restrict__ Kt,
            const float* __restrict__ V, float* __restrict__ O)
{
    extern __shared__ float smem[];
    u64*   q2   = (u64*)smem;                 // 256 u64
    float* sc   = smem + 2*4*DD;              // 16384 f32
    float* red  = sc + TQ * SQ;               // 4096 f32
    float* invz = red + 8 * TQ * DD;          // 8 f32

    const int tid  = threadIdx.x;
    const int lane = tid & 31;
    const int w    = tid >> 5;
    const int h    = blockIdx.y;
    const int n    = blockIdx.z;
    const int nh   = n * HH + h;
    const int l0   = blockIdx.x * TQ;

    // build packed q row-pairs: q2[d*4+j] = {q[2j][d], q[2j+1][d]}
    {
        int d = tid >> 2, j = tid & 3;
        const float* qb = Q + ((size_t)nh * LQ + l0) * DD;
        q2[d * 4 + j] = pk2(qb[(size_t)(2*j) * DD + d], qb[(size_t)(2*j+1) * DD + d]);
    }
    __syncthreads();

    // ---- scores: thread owns one s; accumulators pair query rows ----
    const float* ktb = Kt + (size_t)nh * DD * SQ;
    for (int ss = 0; ss < 8; ss++) {
        int s = ss * 256 + tid;
        const float* kts = ktb + s;
        u64 acc2[4] = {0ull, 0ull, 0ull, 0ull};
#pragma unroll 16
        for (int d = 0; d < DD; d++) {
            u64 kv = dup2(kts[(size_t)d * SQ]);
            ulonglong2 qa = *(const ulonglong2*)&q2[d * 4];
            ulonglong2 qb = *(const ulonglong2*)&q2[d * 4 + 2];
            fma2(acc2[0], qa.x, kv);
            fma2(acc2[1], qa.y, kv);
            fma2(acc2[2], qb.x, kv);
            fma2(acc2[3], qb.y, kv);
        }
#pragma unroll
        for (int j = 0; j < 4; j++) {
            float2 f = up2(acc2[j]);
            sc[(2*j)   * SQ + s] = f.x * 0.125f;
            sc[(2*j+1) * SQ + s] = f.y * 0.125f;
        }
    }
    __syncthreads();

    // ---- per-warp row w: keys, max, exact top-k threshold by counting ----
    {
        unsigned* scU = (unsigned*)(sc + w * SQ);

        // convert to order-preserving keys in place; integer max
        unsigned mxk = 0;
        for (int i = lane; i < SQ; i += 32) {
            unsigned u = __float_as_uint(((float*)scU)[i]);
            unsigned k = (u & 0x80000000u) ? ~u : (u | 0x80000000u);
            scU[i] = k;
            mxk = max(mxk, k);
        }
#pragma unroll
        for (int o = 16; o; o >>= 1) mxk = max(mxk, __shfl_xor_sync(~0u, mxk, o));
        float mx = (mxk & 0x80000000u) ? __uint_as_float(mxk ^ 0x80000000u)
                                       : __uint_as_float(~mxk);

        // find threshold T with count(key >= T) == KSEL (interp + bisect)
        unsigned lo = 0u, hi = 0xFFFFFFFFu, T = 0u;
        int cLo = SQ, cHi = 0;
        bool found = false;
        for (int it = 0; it < 48; it++) {
            unsigned g;
            if (it & 1) {
                g = lo + ((hi - lo) >> 1);
            } else {
                u64 span = (u64)(hi - lo);
                g = lo + (unsigned)(span * (u64)(unsigned)(cLo - KSEL) /
                                    (u64)(unsigned)(cLo - cHi));
            }
            if (g <= lo) g = lo + 1;
            if (g > hi)  g = hi;
            int cnt = 0;
            for (int i = lane; i < SQ; i += 32)
                cnt += __popc(__ballot_sync(0xFFFFFFFFu, scU[i] >= g));
            if (cnt == KSEL) { T = g; found = true; break; }
            if (cnt > KSEL) { lo = g; cLo = cnt; } else { hi = g; cHi = cnt; }
        }
        if (!found) T = lo;   // degenerate tie: keep minimal superset

        // exp + Z, write probs back as floats
        float z = 0.f;
        for (int i = lane; i < SQ; i += 32) {
            unsigned k = scU[i];
            float v = (k & 0x80000000u) ? __uint_as_float(k ^ 0x80000000u)
                                        : __uint_as_float(~k);
            float p = (k >= T) ? __expf(v - mx) : 0.f;
            ((float*)scU)[i] = p;
            z += p;
        }
#pragma unroll
        for (int o = 16; o; o >>= 1) z += __shfl_xor_sync(~0u, z, o);
        if (lane == 0) invz[w] = 1.f / z;
    }
    __syncthreads();

    // ---- attn @ V : warp w handles s in [w*256, w*256+256); lane = d-pair ----
    const u64* vp = (const u64*)(V + (size_t)nh * SQ * DD) + lane;
    u64 acc[TQ];
#pragma unroll
    for (int r = 0; r < TQ; r++) acc[r] = 0ull;

    int sBase = w * 256;
    for (int it = 0; it < 64; it++) {
        int s = sBase + it * 4;
        u64 V0 = vp[(size_t)(s+0) * 32];
        u64 V1 = vp[(size_t)(s+1) * 32];
        u64 V2 = vp[(size_t)(s+2) * 32];
        u64 V3 = vp[(size_t)(s+3) * 32];
#pragma unroll
        for (int r = 0; r < TQ; r++) {
            float4 p = *(const float4*)&sc[r * SQ + s];
            fma2(acc[r], dup2(p.x), V0);
            fma2(acc[r], dup2(p.y), V1);
            fma2(acc[r], dup2(p.z), V2);
            fma2(acc[r], dup2(p.w), V3);
        }
    }
    {
        u64* redp = (u64*)(red + (size_t)w * TQ * DD) + lane;
#pragma unroll
        for (int r = 0; r < TQ; r++) redp[r * 32] = acc[r];
    }
    __syncthreads();

    // ---- cross-warp reduce, normalize, write O[l*N+n][d*H+h] ----
    for (int o = tid; o < TQ * DD; o += 256) {
        int r = o >> 6, d = o & 63;
        float sum = 0.f;
#pragma unroll
        for (int ww = 0; ww < 8; ww++) sum += red[ww * TQ * DD + o];
        float val = sum * invz[r];
        int l = l0 + r;
        O[ ((size_t)(l * NB + n)) * EE + d * HH + h ] = val;
    }
}

// ---------------- launch -----------------------------------------------------
extern "C" void kernel_launch(void* const* d_in, const int* in_sizes, int n_in,
                              void* d_out, int out_size)
{
    const float* query = (const float*)d_in[0];
    const float* key   = (const float*)d_in[1];
    const float* value = (const float*)d_in[2];
    const float* Wq    = (const float*)d_in[3];
    const float* bq    = (const float*)d_in[4];
    const float* Wk    = (const float*)d_in[5];
    const float* bk    = (const float*)d_in[6];
    const float* Wv    = (const float*)d_in[7];
    const float* bv    = (const float*)d_in[8];
    const float* Wo    = (const float*)d_in[9];
    const float* bo    = (const float*)d_in[10];
    float* out = (float*)d_out;

    float *Qp, *Ktp, *Vp, *Op;
    cudaGetSymbolAddress((void**)&Qp,  g_Q);
    cudaGetSymbolAddress((void**)&Ktp, g_Kt);
    cudaGetSymbolAddress((void**)&Vp,  g_V);
    cudaGetSymbolAddress((void**)&Op,  g_O);

    cudaFuncSetAttribute(attn_kernel, cudaFuncAttributeMaxDynamicSharedMemorySize, SMEM_BYTES);

    dim3 gq(GN / BN, GM / BM, 3);   // (8, 32, 3)
    gemm_qkv_kernel<<<gq, 256>>>(query, key, value, Wq, bq, Wk, bk, Wv, bv);

    dim3 ag(LQ / TQ, HH, NB);       // (256, 16, 2)
    attn_kernel<<<ag, 256, SMEM_BYTES>>>(Qp, Ktp, Vp, Op);

    dim3 gg(GN / BN, GM / BM);      // (8, 32)
    gemm_out_kernel<<<gg, 256>>>(Op, Wo, bo, out);
}

// round 5
// speedup vs baseline: 1.1223x; 1.0608x over previous
#include <cuda_runtime.h>
#include <cuda_bf16.h>

#define LQ 2048
#define SQ 2048
#define NB 2
#define EE 1024
#define HH 16
#define DD 64
#define KSEL 1176          // int(2048 * sigmoid(0.3))

#define GM 4096
#define GK 1024
#define GN 1024
#define BM 128
#define BN 128
#define BKK 8
#define LDA 132

#define TQ 16              // query rows per attention CTA
#define SPH 1024           // s-pairs per row

typedef unsigned long long u64;

// ---------------- f32x2 packed helpers (sm_100+) ----------------------------
__device__ __forceinline__ u64 pk2(float lo, float hi) {
    u64 r; asm("mov.b64 %0, {%1, %2};" : "=l"(r) : "f"(lo), "f"(hi)); return r;
}
__device__ __forceinline__ u64 dup2(float x) {
    u64 r; asm("mov.b64 %0, {%1, %1};" : "=l"(r) : "f"(x)); return r;
}
__device__ __forceinline__ void fma2(u64 &d, u64 a, u64 b) {
    asm("fma.rn.f32x2 %0, %1, %2, %0;" : "+l"(d) : "l"(a), "l"(b));
}
__device__ __forceinline__ float2 up2(u64 v) {
    float2 f; asm("mov.b64 {%0, %1}, %2;" : "=f"(f.x), "=f"(f.y) : "l"(v)); return f;
}

// ---------------- scratch ----------------------------------------------------
__device__ float g_Q [ (size_t)NB*HH*LQ*DD ];   // [n,h,l,d]
__device__ float g_Kt[ (size_t)NB*HH*DD*SQ ];   // [n,h,d,s]
__device__ float g_V [ (size_t)NB*HH*SQ*DD ];   // [n,h,s,d]
__device__ float g_O [ (size_t)GM*EE ];         // [l*N+n, e=d*H+h]

// ---------------- GEMM: Y[m,j] = sum_k A[m,k]*W[j,k] + bias[j] --------------
__device__ __forceinline__ void gemm_body(
    const float* __restrict__ A, const float* __restrict__ W,
    const float* __restrict__ bias, float* __restrict__ out, int mode)
{
    __shared__ __align__(16) float As[2][BKK][LDA];
    __shared__ __align__(16) float Bs[2][BKK][LDA];

    const int tid = threadIdx.x;
    const int tx = tid & 15;
    const int ty = tid >> 4;
    const int m0 = blockIdx.y * BM;
    const int n0 = blockIdx.x * BN;
    const int lrow = tid >> 1;        // 0..127
    const int lkq  = (tid & 1) * 4;   // 0 or 4

    const float* Aptr = A + (size_t)(m0 + lrow) * GK + lkq;
    const float* Wptr = W + (size_t)(n0 + lrow) * GK + lkq;

    u64 acc[8][4];
#pragma unroll
    for (int i = 0; i < 8; i++)
#pragma unroll
        for (int j = 0; j < 4; j++) acc[i][j] = 0ull;

    float4 pa = *(const float4*)(Aptr);
    float4 pb = *(const float4*)(Wptr);
    As[0][lkq+0][lrow] = pa.x; As[0][lkq+1][lrow] = pa.y;
    As[0][lkq+2][lrow] = pa.z; As[0][lkq+3][lrow] = pa.w;
    Bs[0][lkq+0][lrow] = pb.x; Bs[0][lkq+1][lrow] = pb.y;
    Bs[0][lkq+2][lrow] = pb.z; Bs[0][lkq+3][lrow] = pb.w;
    __syncthreads();

    int buf = 0;
    for (int k0 = 0; k0 < GK; k0 += BKK) {
        const bool more = (k0 + BKK < GK);
        if (more) {
            pa = *(const float4*)(Aptr + k0 + BKK);
            pb = *(const float4*)(Wptr + k0 + BKK);
        }
#pragma unroll
        for (int kk = 0; kk < BKK; kk++) {
            float4 a0 = *(const float4*)&As[buf][kk][ty * 8];
            float4 a1 = *(const float4*)&As[buf][kk][ty * 8 + 4];
            ulonglong2 b0 = *(const ulonglong2*)&Bs[buf][kk][tx * 4];
            ulonglong2 b1 = *(const ulonglong2*)&Bs[buf][kk][64 + tx * 4];
            float a[8] = {a0.x, a0.y, a0.z, a0.w, a1.x, a1.y, a1.z, a1.w};
#pragma unroll
            for (int i = 0; i < 8; i++) {
                u64 ad = dup2(a[i]);
                fma2(acc[i][0], ad, b0.x);
                fma2(acc[i][1], ad, b0.y);
                fma2(acc[i][2], ad, b1.x);
                fma2(acc[i][3], ad, b1.y);
            }
        }
        if (more) {
            int nb = buf ^ 1;
            As[nb][lkq+0][lrow] = pa.x; As[nb][lkq+1][lrow] = pa.y;
            As[nb][lkq+2][lrow] = pa.z; As[nb][lkq+3][lrow] = pa.w;
            Bs[nb][lkq+0][lrow] = pb.x; Bs[nb][lkq+1][lrow] = pb.y;
            Bs[nb][lkq+2][lrow] = pb.z; Bs[nb][lkq+3][lrow] = pb.w;
        }
        __syncthreads();
        buf ^= 1;
    }

    float bb[8];
#pragma unroll
    for (int j = 0; j < 4; j++) {
        bb[j]     = bias[n0 + tx * 4 + j];
        bb[4 + j] = bias[n0 + 64 + tx * 4 + j];
    }

#pragma unroll
    for (int i = 0; i < 8; i++) {
        int m = m0 + ty * 8 + i;
        int l = m >> 1;
        int nn = m & 1;
        float2 f0 = up2(acc[i][0]);
        float2 f1 = up2(acc[i][1]);
        float2 f2 = up2(acc[i][2]);
        float2 f3 = up2(acc[i][3]);
        float vv[8] = { f0.x + bb[0], f0.y + bb[1], f1.x + bb[2], f1.y + bb[3],
                        f2.x + bb[4], f2.y + bb[5], f3.x + bb[6], f3.y + bb[7] };
#pragma unroll
        for (int j = 0; j < 8; j++) {
            int c = (j < 4) ? (n0 + tx * 4 + j) : (n0 + 64 + tx * 4 + (j - 4));
            int h = c >> 6, d = c & 63;
            float v = vv[j];
            if (mode == 0)      g_Q [ (((size_t)(nn*HH + h))*LQ + l)*DD + d ] = v;
            else if (mode == 1) g_Kt[ (((size_t)(nn*HH + h))*DD + d)*SQ + l ] = v;
            else if (mode == 2) g_V [ (((size_t)(nn*HH + h))*SQ + l)*DD + d ] = v;
            else                out [ (size_t)m * GN + c ] = v;
        }
    }
}

__global__ void __launch_bounds__(256, 2) gemm_qkv_kernel(
    const float* __restrict__ q, const float* __restrict__ k, const float* __restrict__ v,
    const float* __restrict__ Wq, const float* __restrict__ bq,
    const float* __restrict__ Wk, const float* __restrict__ bk,
    const float* __restrict__ Wv, const float* __restrict__ bv)
{
    int z = blockIdx.z;
    const float* A = (z == 0) ? q  : (z == 1) ? k  : v;
    const float* W = (z == 0) ? Wq : (z == 1) ? Wk : Wv;
    const float* B = (z == 0) ? bq : (z == 1) ? bk : bv;
    gemm_body(A, W, B, nullptr, z);
}

__global__ void __launch_bounds__(256, 2) gemm_out_kernel(
    const float* __restrict__ A, const float* __restrict__ W,
    const float* __restrict__ b, float* __restrict__ out)
{
    gemm_body(A, W, b, out, 3);
}

// ---------------- attention --------------------------------------------------
// smem (u64 units): q2d[64*16] | scp[16*1024] | red f32[16*16*64] | invz f32[16]
#define SMEM_BYTES_ATTN ((1024 + 16*1024) * 8 + (16*16*64) * 4 + 16 * 4)

__device__ __forceinline__ unsigned f2key(float f) {
    unsigned u = __float_as_uint(f);
    return (u & 0x80000000u) ? ~u : (u | 0x80000000u);
}
__device__ __forceinline__ float key2f(unsigned k) {
    return (k & 0x80000000u) ? __uint_as_float(k ^ 0x80000000u) : __uint_as_float(~k);
}

__global__ void __launch_bounds__(512, 1)
attn_kernel(const float* __restrict__ Q, const float* __restrict__ Kt,
            const float* __restrict__ V, float* __restrict__ O)
{
    extern __shared__ __align__(16) u64 sm[];
    u64*   q2d  = sm;                    // [d][r] : dup'd q * 0.125
    u64*   scp  = sm + 1024;             // [r][sp] : {sc[r][2sp], sc[r][2sp+1]}
    float* red  = (float*)(sm + 1024 + 16 * 1024);   // [w][r][d]
    float* invz = red + 16 * 16 * 64;

    const int tid  = threadIdx.x;
    const int lane = tid & 31;
    const int w    = tid >> 5;
    const int h    = blockIdx.y;
    const int n    = blockIdx.z;
    const int nh   = n * HH + h;
    const int l0   = blockIdx.x * TQ;

    // build dup'd q: q2d[d*16 + r] = {q[r][d]*s, q[r][d]*s}
    {
        const float* qb = Q + ((size_t)nh * LQ + l0) * DD;
#pragma unroll
        for (int t = tid; t < 1024; t += 512) {
            int d = t >> 4, r = t & 15;
            q2d[d * 16 + r] = dup2(qb[(size_t)r * DD + d] * 0.125f);
        }
    }
    __syncthreads();

    // ---- scores: thread owns s-pair sp; acc[r] pairs (s0, s1) ----
    const u64* ktp = (const u64*)(Kt + (size_t)nh * DD * SQ);
    for (int half = 0; half < 2; half++) {
        int sp = half * 512 + tid;
        const u64* kp = ktp + sp;
        u64 acc[16];
#pragma unroll
        for (int r = 0; r < 16; r++) acc[r] = 0ull;
#pragma unroll 8
        for (int d = 0; d < DD; d++) {
            u64 kv = kp[(size_t)d * SPH];
            const u64* qd = q2d + d * 16;
#pragma unroll
            for (int r8 = 0; r8 < 8; r8++) {
                ulonglong2 qq = *(const ulonglong2*)(qd + r8 * 2);
                fma2(acc[r8 * 2],     qq.x, kv);
                fma2(acc[r8 * 2 + 1], qq.y, kv);
            }
        }
#pragma unroll
        for (int r = 0; r < 16; r++) scp[r * SPH + sp] = acc[r];
    }
    __syncthreads();

    // ---- per-warp row w: keys, max, exact top-k threshold, exp, Z ----
    {
        u64* P = scp + w * SPH;
        unsigned mxk = 0;
        for (int i = lane; i < SPH; i += 32) {
            float2 f = up2(P[i]);
            unsigned k0 = f2key(f.x), k1 = f2key(f.y);
            mxk = max(mxk, max(k0, k1));
            P[i] = ((u64)k1 << 32) | (u64)k0;
        }
#pragma unroll
        for (int o = 16; o; o >>= 1) mxk = max(mxk, __shfl_xor_sync(~0u, mxk, o));
        float mx = key2f(mxk);

        unsigned lo = 0u, hi = 0xFFFFFFFFu, T = 0u;
        int cLo = SQ, cHi = 0;
        bool found = false;
        for (int it = 0; it < 48; it++) {
            unsigned g;
            if (it & 1) {
                g = lo + ((hi - lo) >> 1);
            } else {
                u64 span = (u64)(hi - lo);
                g = lo + (unsigned)(span * (u64)(unsigned)(cLo - KSEL) /
                                    (u64)(unsigned)(cLo - cHi));
            }
            if (g <= lo) g = lo + 1;
            if (g > hi)  g = hi;
            int cnt = 0;
            for (int i = lane; i < SPH; i += 32) {
                u64 v = P[i];
                unsigned k0 = (unsigned)v, k1 = (unsigned)(v >> 32);
                cnt += __popc(__ballot_sync(0xFFFFFFFFu, k0 >= g));
                cnt += __popc(__ballot_sync(0xFFFFFFFFu, k1 >= g));
            }
            if (cnt == KSEL) { T = g; found = true; break; }
            if (cnt > KSEL) { lo = g; cLo = cnt; } else { hi = g; cHi = cnt; }
        }
        if (!found) T = lo;

        float z = 0.f;
        for (int i = lane; i < SPH; i += 32) {
            u64 v = P[i];
            unsigned k0 = (unsigned)v, k1 = (unsigned)(v >> 32);
            float p0 = (k0 >= T) ? __expf(key2f(k0) - mx) : 0.f;
            float p1 = (k1 >= T) ? __expf(key2f(k1) - mx) : 0.f;
            P[i] = pk2(p0, p1);
            z += p0 + p1;
        }
#pragma unroll
        for (int o = 16; o; o >>= 1) z += __shfl_xor_sync(~0u, z, o);
        if (lane == 0) invz[w] = 1.f / z;
    }
    __syncthreads();

    // ---- attn @ V : warp w handles sp in [w*64, w*64+64); lane -> d = 2l, 2l+1 ----
    {
        const float* vbase = V + (size_t)nh * SQ * DD + 2 * lane;
        u64 accA[16], accB[16];
#pragma unroll
        for (int r = 0; r < 16; r++) { accA[r] = 0ull; accB[r] = 0ull; }
        int sp0 = w * 64;
#pragma unroll 2
        for (int it = 0; it < 64; it++) {
            int sp = sp0 + it;
            float2 v0 = *(const float2*)(vbase + (size_t)(2 * sp)     * DD);
            float2 v1 = *(const float2*)(vbase + (size_t)(2 * sp + 1) * DD);
            u64 bd0 = pk2(v0.x, v1.x);
            u64 bd1 = pk2(v0.y, v1.y);
#pragma unroll
            for (int r = 0; r < 16; r++) {
                u64 pp = scp[r * SPH + sp];
                fma2(accA[r], pp, bd0);
                fma2(accB[r], pp, bd1);
            }
        }
        float* rw = red + w * 16 * 64;
#pragma unroll
        for (int r = 0; r < 16; r++) {
            float2 a = up2(accA[r]);
            float2 b = up2(accB[r]);
            rw[r * 64 + 2 * lane]     = a.x + a.y;
            rw[r * 64 + 2 * lane + 1] = b.x + b.y;
        }
    }
    __syncthreads();

    // ---- cross-warp reduce, normalize, write O ----
    for (int t = tid; t < 16 * 64; t += 512) {
        int r = t >> 6, d = t & 63;
        float s = 0.f;
#pragma unroll
        for (int ww = 0; ww < 16; ww++) s += red[ww * 1024 + t];
        s *= invz[r];
        int l = l0 + r;
        O[ ((size_t)(l * NB + n)) * EE + d * HH + h ] = s;
    }
}

// ---------------- launch -----------------------------------------------------
extern "C" void kernel_launch(void* const* d_in, const int* in_sizes, int n_in,
                              void* d_out, int out_size)
{
    const float* query = (const float*)d_in[0];
    const float* key   = (const float*)d_in[1];
    const float* value = (const float*)d_in[2];
    const float* Wq    = (const float*)d_in[3];
    const float* bq    = (const float*)d_in[4];
    const float* Wk    = (const float*)d_in[5];
    const float* bk    = (const float*)d_in[6];
    const float* Wv    = (const float*)d_in[7];
    const float* bv    = (const float*)d_in[8];
    const float* Wo    = (const float*)d_in[9];
    const float* bo    = (const float*)d_in[10];
    float* out = (float*)d_out;

    float *Qp, *Ktp, *Vp, *Op;
    cudaGetSymbolAddress((void**)&Qp,  g_Q);
    cudaGetSymbolAddress((void**)&Ktp, g_Kt);
    cudaGetSymbolAddress((void**)&Vp,  g_V);
    cudaGetSymbolAddress((void**)&Op,  g_O);

    cudaFuncSetAttribute(attn_kernel, cudaFuncAttributeMaxDynamicSharedMemorySize, SMEM_BYTES_ATTN);

    dim3 gq(GN / BN, GM / BM, 3);   // (8, 32, 3)
    gemm_qkv_kernel<<<gq, 256>>>(query, key, value, Wq, bq, Wk, bk, Wv, bv);

    dim3 ag(LQ / TQ, HH, NB);       // (128, 16, 2)
    attn_kernel<<<ag, 512, SMEM_BYTES_ATTN>>>(Qp, Ktp, Vp, Op);

    dim3 gg(GN / BN, GM / BM);      // (8, 32)
    gemm_out_kernel<<<gg, 256>>>(Op, Wo, bo, out);
}